// round 4
// baseline (speedup 1.0000x reference)
#include <cuda_runtime.h>
#include <math.h>

// Problem constants (fixed shapes)
#define NB   64      // batch N
#define CIN  64      // in channels C
#define TT   300     // time T
#define VV   25      // vertices V
#define TVN  7500    // T*V
#define CI   16      // inter channels
#define CO   64      // out channels
#define NS   3       // subsets
#define KCT  4800    // CI*T

// Scratch (device globals; allocation is forbidden)
__device__ float g_a[(size_t)NS * NB * CI * TVN];   // (s,n,ci,t,v) == per-(s,n) 4800x25 row-major
__device__ float g_b[(size_t)NS * NB * CI * TVN];
__device__ float g_attn[NS * NB * VV * VV];         // (s,n,u,v)

// ---------------------------------------------------------------------------
// Kernel 1: a = Wa@x + ba, b = Wb@x + bb  for all 3 subsets at once.
// Per n: Out[96][7500] = W96[96][64] @ X[64][7500]
// rows 0..47 -> a (s*16+ci), rows 48..95 -> b
// ---------------------------------------------------------------------------
__global__ __launch_bounds__(256) void k_ab(
    const float* __restrict__ x,
    const float* __restrict__ Wa, const float* __restrict__ ba,
    const float* __restrict__ Wb, const float* __restrict__ bb)
{
    __shared__ float Wsm[96][64];     // 24 KB
    __shared__ float Xsm[32][128];    // 16 KB

    const int n    = blockIdx.y;
    const int col0 = blockIdx.x * 128;
    const int tid  = threadIdx.x;

    for (int idx = tid; idx < 96 * 64; idx += 256) {
        int r = idx >> 6, k = idx & 63;
        Wsm[r][k] = (r < 48) ? Wa[r * 64 + k] : Wb[(r - 48) * 64 + k];
    }

    float acc[12][4];
#pragma unroll
    for (int i = 0; i < 12; i++)
#pragma unroll
        for (int q = 0; q < 4; q++) acc[i][q] = 0.f;

    const int tx = tid & 31, ty = tid >> 5;
    const float* xb = x + (size_t)n * CIN * TVN;

    for (int kc = 0; kc < 2; kc++) {
        __syncthreads();
        for (int idx = tid; idx < 32 * 128; idx += 256) {
            int c = idx >> 7, cc = idx & 127;
            int col = col0 + cc;
            Xsm[c][cc] = (col < TVN) ? xb[(size_t)(kc * 32 + c) * TVN + col] : 0.f;
        }
        __syncthreads();
#pragma unroll 8
        for (int k = 0; k < 32; k++) {
            float xv[4];
#pragma unroll
            for (int q = 0; q < 4; q++) xv[q] = Xsm[k][tx + 32 * q];
#pragma unroll
            for (int i = 0; i < 12; i++) {
                float w = Wsm[ty * 12 + i][kc * 32 + k];
#pragma unroll
                for (int q = 0; q < 4; q++) acc[i][q] = fmaf(w, xv[q], acc[i][q]);
            }
        }
    }

#pragma unroll
    for (int i = 0; i < 12; i++) {
        int r = ty * 12 + i;
        int which = (r >= 48);
        int rr = which ? r - 48 : r;   // s*16 + ci
        float bias = which ? bb[rr] : ba[rr];
        int s  = rr >> 4, ci = rr & 15;
        float* dst = (which ? g_b : g_a) +
                     ((size_t)(s * NB + n) * CI + ci) * TVN;
#pragma unroll
        for (int q = 0; q < 4; q++) {
            int col = col0 + tx + 32 * q;
            if (col < TVN) dst[col] = acc[i][q] + bias;
        }
    }
}

// ---------------------------------------------------------------------------
// Kernel 2: per (s,n): G[u,v] = (1/4800) * sum_k a[k,u]*b[k,v]  (k = ci*T+t)
// then softmax over u (axis -2), + (A_static + graph_attn), store attn.
// a/b per (s,n) are contiguous 4800x25 row-major matrices.
// Threads 0..124 accumulate: thread owns u = tid/5, v in [ (tid%5)*5, +5 )
// ---------------------------------------------------------------------------
__global__ __launch_bounds__(256) void k_attn(
    const float* __restrict__ Ast, const float* __restrict__ Gat)
{
    const int sn = blockIdx.x;          // s*64 + n
    const int s  = sn >> 6;
    const float* Abase = g_a + (size_t)sn * (CI * TVN);
    const float* Bbase = g_b + (size_t)sn * (CI * TVN);

    __shared__ float at[32 * 25];
    __shared__ float bt[32 * 25];
    __shared__ float Gsm[625];

    const int tid = threadIdx.x;
    const int u   = tid / 5;
    const int v0  = (tid % 5) * 5;
    const bool act = (tid < 125);

    float acc[5] = {0.f, 0.f, 0.f, 0.f, 0.f};

    // register prefetch pipeline (800 floats per chunk, 4 per thread)
    float pa[4], pb[4];
#pragma unroll
    for (int q = 0; q < 4; q++) {
        int idx = tid + 256 * q;
        if (idx < 800) { pa[q] = Abase[idx]; pb[q] = Bbase[idx]; }
    }

    for (int kc = 0; kc < 150; kc++) {
        __syncthreads();           // previous compute done before overwrite
#pragma unroll
        for (int q = 0; q < 4; q++) {
            int idx = tid + 256 * q;
            if (idx < 800) { at[idx] = pa[q]; bt[idx] = pb[q]; }
        }
        __syncthreads();
        if (kc < 149) {
            const float* An = Abase + (kc + 1) * 800;
            const float* Bn = Bbase + (kc + 1) * 800;
#pragma unroll
            for (int q = 0; q < 4; q++) {
                int idx = tid + 256 * q;
                if (idx < 800) { pa[q] = An[idx]; pb[q] = Bn[idx]; }
            }
        }
        if (act) {
#pragma unroll 8
            for (int kk = 0; kk < 32; kk++) {
                float av = at[kk * 25 + u];
#pragma unroll
                for (int j = 0; j < 5; j++)
                    acc[j] = fmaf(av, bt[kk * 25 + v0 + j], acc[j]);
            }
        }
    }

    __syncthreads();
    if (act) {
#pragma unroll
        for (int j = 0; j < 5; j++)
            Gsm[u * 25 + v0 + j] = acc[j] * (1.0f / 4800.0f);
    }
    __syncthreads();

    if (tid < 25) {
        const int v = tid;
        float m = -INFINITY;
        for (int uu = 0; uu < 25; uu++) m = fmaxf(m, Gsm[uu * 25 + v]);
        float ssum = 0.f;
        for (int uu = 0; uu < 25; uu++) {
            float e = expf(Gsm[uu * 25 + v] - m);
            Gsm[uu * 25 + v] = e;
            ssum += e;
        }
        float sinv = 1.0f / ssum;
        float* dst = g_attn + (size_t)sn * 625;
        const float* a1 = Ast + s * 625;
        const float* a2 = Gat + s * 625;
        for (int uu = 0; uu < 25; uu++) {
            int i = uu * 25 + v;
            dst[i] = Gsm[i] * sinv + a1[i] + a2[i];
        }
    }
}

// ---------------------------------------------------------------------------
// Kernel 3: fused  Y[s,c,(t,v)] = sum_u x[c,(t,u)] * attn[s,u,v]
//                  h[o,(t,v)]   = sum_{s,c} Wg[s,o,c] * Y[s,c,(t,v)] + sum_s bg[s,o]
//                  out = relu( BN(h) + x )
// One block per (n, 4-t tile). 320 threads.
// ---------------------------------------------------------------------------
#define W2S 193   // padded row stride of W2 in smem

__global__ __launch_bounds__(320, 1) void k_out(
    const float* __restrict__ x,
    const float* __restrict__ Wg, const float* __restrict__ bg,
    const float* __restrict__ gamma, const float* __restrict__ beta,
    const float* __restrict__ rmean, const float* __restrict__ rvar,
    float* __restrict__ out)
{
    extern __shared__ float sm[];
    float* attn_sm = sm;                 // 3*625       = 1875
    float* W2      = attn_sm + 1875;     // 64*193      = 12352
    float* xsm     = W2 + 12352;         // 64*100      = 6400
    float* Ysm     = xsm + 6400;         // 192*100     = 19200

    const int n   = blockIdx.y;
    const int t0  = blockIdx.x * 4;      // 4 t's -> 100 cols
    const int tid = threadIdx.x;

    // loads
    for (int idx = tid; idx < 1875; idx += 320) {
        int s = idx / 625;
        attn_sm[idx] = g_attn[(size_t)(s * NB + n) * 625 + (idx - s * 625)];
    }
    for (int idx = tid; idx < 64 * 192; idx += 320) {
        int o = idx / 192, sc = idx - o * 192;
        int s = sc >> 6, c = sc & 63;
        W2[o * W2S + sc] = Wg[(s * CO + o) * CIN + c];
    }
    {
        const float* xb = x + (size_t)n * CIN * TVN + t0 * 25;
        for (int idx = tid; idx < 6400; idx += 320) {
            int c = idx / 100, cc = idx - c * 100;
            xsm[idx] = xb[(size_t)c * TVN + cc];
        }
    }
    __syncthreads();

    // Stage A: 960 tiles of 4c x 5v  (3 passes of 320)
#pragma unroll
    for (int p = 0; p < 3; p++) {
        int tileid = p * 320 + tid;
        int vg = tileid % 5;            // v0 = vg*5
        int cg = (tileid / 5) & 15;     // c0 = cg*4
        int st = tileid / 80;           // s*4 + t
        int s  = st >> 2, t = st & 3;
        int v0 = vg * 5, c0 = cg * 4;
        float a2[4][5];
#pragma unroll
        for (int i = 0; i < 4; i++)
#pragma unroll
            for (int j = 0; j < 5; j++) a2[i][j] = 0.f;
        const float* ap = attn_sm + s * 625 + v0;
#pragma unroll 5
        for (int u = 0; u < 25; u++) {
            float xv[4];
#pragma unroll
            for (int i = 0; i < 4; i++) xv[i] = xsm[(c0 + i) * 100 + t * 25 + u];
            float av[5];
#pragma unroll
            for (int j = 0; j < 5; j++) av[j] = ap[u * 25 + j];
#pragma unroll
            for (int i = 0; i < 4; i++)
#pragma unroll
                for (int j = 0; j < 5; j++)
                    a2[i][j] = fmaf(xv[i], av[j], a2[i][j]);
        }
#pragma unroll
        for (int i = 0; i < 4; i++)
#pragma unroll
            for (int j = 0; j < 5; j++)
                Ysm[(s * 64 + c0 + i) * 100 + t * 25 + v0 + j] = a2[i][j];
    }
    __syncthreads();

    // Stage B: 320 tiles of 4o x 5col
    const int og   = tid & 15;           // o0 = og*4
    const int colg = tid >> 4;           // col0 = colg*5  (0..19)
    const int o0   = og * 4, col0 = colg * 5;
    float bcc[4][5];
#pragma unroll
    for (int i = 0; i < 4; i++)
#pragma unroll
        for (int j = 0; j < 5; j++) bcc[i][j] = 0.f;

#pragma unroll 4
    for (int k = 0; k < 192; k++) {
        float wv[4];
#pragma unroll
        for (int i = 0; i < 4; i++) wv[i] = W2[(o0 + i) * W2S + k];
        float yv[5];
#pragma unroll
        for (int j = 0; j < 5; j++) yv[j] = Ysm[k * 100 + col0 + j];
#pragma unroll
        for (int i = 0; i < 4; i++)
#pragma unroll
            for (int j = 0; j < 5; j++)
                bcc[i][j] = fmaf(wv[i], yv[j], bcc[i][j]);
    }
    __syncthreads();   // all Ysm reads done before reuse as output staging

#pragma unroll
    for (int i = 0; i < 4; i++)
#pragma unroll
        for (int j = 0; j < 5; j++)
            Ysm[(o0 + i) * 100 + col0 + j] = bcc[i][j];
    __syncthreads();

    // epilogue: bias sum, BN, residual, relu; coalesced store
    float* ob = out + (size_t)n * CIN * TVN + t0 * 25;
    for (int idx = tid; idx < 6400; idx += 320) {
        int o = idx / 100, cc = idx - o * 100;
        float h = Ysm[idx] + bg[o] + bg[64 + o] + bg[128 + o];
        float inv = gamma[o] * rsqrtf(rvar[o] + 1e-5f);
        float r = (h - rmean[o]) * inv + beta[o] + xsm[idx];
        ob[(size_t)o * TVN + cc] = fmaxf(r, 0.f);
    }
}

// ---------------------------------------------------------------------------
extern "C" void kernel_launch(void* const* d_in, const int* in_sizes, int n_in,
                              void* d_out, int out_size)
{
    const float* x     = (const float*)d_in[0];
    const float* Ast   = (const float*)d_in[1];
    const float* Gat   = (const float*)d_in[2];
    const float* Wg    = (const float*)d_in[3];
    const float* bg    = (const float*)d_in[4];
    const float* Wa    = (const float*)d_in[5];
    const float* ba    = (const float*)d_in[6];
    const float* Wb    = (const float*)d_in[7];
    const float* bb    = (const float*)d_in[8];
    const float* gamma = (const float*)d_in[9];
    const float* beta  = (const float*)d_in[10];
    const float* rmean = (const float*)d_in[11];
    const float* rvar  = (const float*)d_in[12];
    float* out = (float*)d_out;

    (void)in_sizes; (void)n_in; (void)out_size;

    const int smem_k3 = (1875 + 64 * W2S + 6400 + 19200) * (int)sizeof(float);
    cudaFuncSetAttribute(k_out, cudaFuncAttributeMaxDynamicSharedMemorySize, smem_k3);

    k_ab<<<dim3(59, 64), 256>>>(x, Wa, ba, Wb, bb);
    k_attn<<<192, 256>>>(Ast, Gat);
    k_out<<<dim3(75, 64), 320, smem_k3>>>(x, Wg, bg, gamma, beta, rmean, rvar, out);
}

// round 7
// speedup vs baseline: 1.3171x; 1.3171x over previous
#include <cuda_runtime.h>
#include <math.h>

// Problem constants (fixed shapes)
#define NB   64      // batch N
#define CIN  64      // in channels C
#define TT   300     // time T
#define VV   25      // vertices V
#define TVN  7500    // T*V
#define CI   16      // inter channels
#define CO   64      // out channels
#define NS   3       // subsets
#define KCT  4800    // CI*T

// Scratch (device globals; allocation is forbidden)
__device__ float g_a[(size_t)NS * NB * CI * TVN];   // per-(s,n) 4800x25 row-major
__device__ float g_b[(size_t)NS * NB * CI * TVN];
__device__ float g_z[(size_t)NS * NB * CO * TVN];   // z_s = Wg_s @ x (no bias)
__device__ float g_attn[NS * NB * VV * VV];         // (s,n,u,v)

// ---------------------------------------------------------------------------
// Kernel 1 (k_mm): one GEMM template, three row-groups via blockIdx.z:
//   gz=0: rows 0..47 -> a = Wa@x (+ba), rows 48..95 -> b = Wb@x (+bb)
//   gz=1: z rows   0..95  = Wg rows   0..95  @ x   (no bias)
//   gz=2: z rows  96..191 = Wg rows  96..191 @ x   (no bias)
// Per n: Out[96][7500] = W[96][64] @ X[64][7500]
// ---------------------------------------------------------------------------
__global__ __launch_bounds__(256) void k_mm(
    const float* __restrict__ x,
    const float* __restrict__ Wa, const float* __restrict__ ba,
    const float* __restrict__ Wb, const float* __restrict__ bb,
    const float* __restrict__ Wg)
{
    __shared__ float Wsm[96][64];     // 24 KB
    __shared__ float Xsm[32][128];    // 16 KB

    const int n    = blockIdx.y;
    const int col0 = blockIdx.x * 128;
    const int gz   = blockIdx.z;
    const int tid  = threadIdx.x;

    for (int idx = tid; idx < 96 * 64; idx += 256) {
        int r = idx >> 6, k = idx & 63;
        float w;
        if (gz == 0) w = (r < 48) ? Wa[r * 64 + k] : Wb[(r - 48) * 64 + k];
        else         w = Wg[((gz - 1) * 96 + r) * 64 + k];
        Wsm[r][k] = w;
    }

    float acc[12][4];
#pragma unroll
    for (int i = 0; i < 12; i++)
#pragma unroll
        for (int q = 0; q < 4; q++) acc[i][q] = 0.f;

    const int tx = tid & 31, ty = tid >> 5;
    const float* xb = x + (size_t)n * CIN * TVN;

    for (int kc = 0; kc < 2; kc++) {
        __syncthreads();
        for (int idx = tid; idx < 32 * 128; idx += 256) {
            int c = idx >> 7, cc = idx & 127;
            int col = col0 + cc;
            Xsm[c][cc] = (col < TVN) ? xb[(size_t)(kc * 32 + c) * TVN + col] : 0.f;
        }
        __syncthreads();
#pragma unroll 8
        for (int k = 0; k < 32; k++) {
            float xv[4];
#pragma unroll
            for (int q = 0; q < 4; q++) xv[q] = Xsm[k][tx + 32 * q];
#pragma unroll
            for (int i = 0; i < 12; i++) {
                float w = Wsm[ty * 12 + i][kc * 32 + k];
#pragma unroll
                for (int q = 0; q < 4; q++) acc[i][q] = fmaf(w, xv[q], acc[i][q]);
            }
        }
    }

#pragma unroll
    for (int i = 0; i < 12; i++) {
        int r = ty * 12 + i;
        float* dst;
        float bias;
        if (gz == 0) {
            int which = (r >= 48);
            int rr = which ? r - 48 : r;       // s*16 + ci
            bias = which ? bb[rr] : ba[rr];
            int s = rr >> 4, ci = rr & 15;
            dst = (which ? g_b : g_a) + ((size_t)(s * NB + n) * CI + ci) * TVN;
        } else {
            int zr = (gz - 1) * 96 + r;        // s*64 + o
            int s = zr >> 6, o = zr & 63;
            bias = 0.f;
            dst = g_z + ((size_t)(s * NB + n) * CO + o) * TVN;
        }
#pragma unroll
        for (int q = 0; q < 4; q++) {
            int col = col0 + tx + 32 * q;
            if (col < TVN) dst[col] = acc[i][q] + bias;
        }
    }
}

// ---------------------------------------------------------------------------
// Kernel 2: per (s,n): G[u,v] = (1/4800) * sum_k a[k,u]*b[k,v]  (k = ci*T+t)
// then softmax over u (axis -2), + (A_static + graph_attn), store attn.
// ---------------------------------------------------------------------------
__global__ __launch_bounds__(256) void k_attn(
    const float* __restrict__ Ast, const float* __restrict__ Gat)
{
    const int sn = blockIdx.x;          // s*64 + n
    const int s  = sn >> 6;
    const float* Abase = g_a + (size_t)sn * (CI * TVN);
    const float* Bbase = g_b + (size_t)sn * (CI * TVN);

    __shared__ float at[32 * 25];
    __shared__ float bt[32 * 25];
    __shared__ float Gsm[625];

    const int tid = threadIdx.x;
    const int u   = tid / 5;
    const int v0  = (tid % 5) * 5;
    const bool act = (tid < 125);

    float acc[5] = {0.f, 0.f, 0.f, 0.f, 0.f};

    float pa[4], pb[4];
#pragma unroll
    for (int q = 0; q < 4; q++) {
        int idx = tid + 256 * q;
        if (idx < 800) { pa[q] = Abase[idx]; pb[q] = Bbase[idx]; }
    }

    for (int kc = 0; kc < 150; kc++) {
        __syncthreads();
#pragma unroll
        for (int q = 0; q < 4; q++) {
            int idx = tid + 256 * q;
            if (idx < 800) { at[idx] = pa[q]; bt[idx] = pb[q]; }
        }
        __syncthreads();
        if (kc < 149) {
            const float* An = Abase + (kc + 1) * 800;
            const float* Bn = Bbase + (kc + 1) * 800;
#pragma unroll
            for (int q = 0; q < 4; q++) {
                int idx = tid + 256 * q;
                if (idx < 800) { pa[q] = An[idx]; pb[q] = Bn[idx]; }
            }
        }
        if (act) {
#pragma unroll 8
            for (int kk = 0; kk < 32; kk++) {
                float av = at[kk * 25 + u];
#pragma unroll
                for (int j = 0; j < 5; j++)
                    acc[j] = fmaf(av, bt[kk * 25 + v0 + j], acc[j]);
            }
        }
    }

    __syncthreads();
    if (act) {
#pragma unroll
        for (int j = 0; j < 5; j++)
            Gsm[u * 25 + v0 + j] = acc[j] * (1.0f / 4800.0f);
    }
    __syncthreads();

    if (tid < 25) {
        const int v = tid;
        float m = -INFINITY;
        for (int uu = 0; uu < 25; uu++) m = fmaxf(m, Gsm[uu * 25 + v]);
        float ssum = 0.f;
        for (int uu = 0; uu < 25; uu++) {
            float e = expf(Gsm[uu * 25 + v] - m);
            Gsm[uu * 25 + v] = e;
            ssum += e;
        }
        float sinv = 1.0f / ssum;
        float* dst = g_attn + (size_t)sn * 625;
        const float* a1 = Ast + s * 625;
        const float* a2 = Gat + s * 625;
        for (int uu = 0; uu < 25; uu++) {
            int i = uu * 25 + v;
            dst[i] = Gsm[i] * sinv + a1[i] + a2[i];
        }
    }
}

// ---------------------------------------------------------------------------
// Kernel 3 (k_out2): out[o,t,v] = relu( BN( sum_{s,u} z[s,o,t,u]*attn[s,u,v]
//                                         + sum_s bg[s,o] ) + x )
// K = 75 (s,u). Block = (n, 4-t tile), 320 threads, 2 CTAs/SM.
// zsm stored transposed: zsm[k][row], row = t*64 + o  (float4 row loads)
// ---------------------------------------------------------------------------
#define ZS 260    // zsm row stride (mult of 4 for float4 alignment)
#define AS 26     // attn row stride

__global__ __launch_bounds__(320) void k_out2(
    const float* __restrict__ x,
    const float* __restrict__ bg,
    const float* __restrict__ gamma, const float* __restrict__ beta,
    const float* __restrict__ rmean, const float* __restrict__ rvar,
    float* __restrict__ out)
{
    extern __shared__ float sm[];
    float* zsm = sm;                   // 75*260 = 19500
    float* atn = zsm + 75 * ZS;        // 75*26  = 1950
    float* sc  = atn + 75 * AS;        // 64
    float* sh  = sc + 64;              // 64

    const int n   = blockIdx.y;
    const int t0  = blockIdx.x * 4;
    const int tid = threadIdx.x;

    // attn -> smem, keyed by k = s*25+u
    for (int idx = tid; idx < 1875; idx += 320) {
        int s = idx / 625, rem = idx - s * 625;    // rem = u*25+v
        int u = rem / 25, v = rem - u * 25;
        atn[(s * 25 + u) * AS + v] = g_attn[(size_t)(s * NB + n) * 625 + rem];
    }
    // z -> smem transposed: zsm[s*25+u][tt*64+o]
    for (int idx = tid; idx < 19200; idx += 320) {
        int seg = idx / 100, pos = idx - seg * 100;   // seg = s*64+o, pos = tt*25+u
        int s = seg >> 6, o = seg & 63;
        int tt = pos / 25, u = pos - tt * 25;
        zsm[(s * 25 + u) * ZS + tt * 64 + o] =
            g_z[((size_t)(s * NB + n) * CO + o) * TVN + t0 * 25 + pos];
    }
    if (tid < 64) {
        float inv = rsqrtf(rvar[tid] + 1e-5f);
        float s0 = gamma[tid] * inv;
        float bsum = bg[tid] + bg[64 + tid] + bg[128 + tid];
        sc[tid] = s0;
        sh[tid] = beta[tid] + (bsum - rmean[tid]) * s0;
    }
    __syncthreads();

    const int rg = tid / 5, cg = tid - rg * 5;
    const int r0 = rg * 4, v0 = cg * 5;
    const int t  = r0 >> 6, o0 = r0 & 63;

    float acc[4][5];
#pragma unroll
    for (int i = 0; i < 4; i++)
#pragma unroll
        for (int j = 0; j < 5; j++) acc[i][j] = 0.f;

#pragma unroll 5
    for (int k = 0; k < 75; k++) {
        float4 zq = *reinterpret_cast<const float4*>(&zsm[k * ZS + r0]);
        float av[5];
#pragma unroll
        for (int j = 0; j < 5; j++) av[j] = atn[k * AS + v0 + j];
        float zz[4] = {zq.x, zq.y, zq.z, zq.w};
#pragma unroll
        for (int i = 0; i < 4; i++)
#pragma unroll
            for (int j = 0; j < 5; j++)
                acc[i][j] = fmaf(zz[i], av[j], acc[i][j]);
    }

    // epilogue: BN + bias-sum + residual + relu, straight to global
    const float* xb = x + (size_t)n * CIN * TVN;
    float* ob = out + (size_t)n * CIN * TVN;
#pragma unroll
    for (int i = 0; i < 4; i++) {
        int o = o0 + i;
        size_t base = (size_t)o * TVN + (t0 + t) * 25 + v0;
        float s0 = sc[o], h0 = sh[o];
#pragma unroll
        for (int j = 0; j < 5; j++) {
            float val = acc[i][j] * s0 + h0 + xb[base + j];
            ob[base + j] = fmaxf(val, 0.f);
        }
    }
}

// ---------------------------------------------------------------------------
extern "C" void kernel_launch(void* const* d_in, const int* in_sizes, int n_in,
                              void* d_out, int out_size)
{
    const float* x     = (const float*)d_in[0];
    const float* Ast   = (const float*)d_in[1];
    const float* Gat   = (const float*)d_in[2];
    const float* Wg    = (const float*)d_in[3];
    const float* bg    = (const float*)d_in[4];
    const float* Wa    = (const float*)d_in[5];
    const float* ba    = (const float*)d_in[6];
    const float* Wb    = (const float*)d_in[7];
    const float* bb    = (const float*)d_in[8];
    const float* gamma = (const float*)d_in[9];
    const float* beta  = (const float*)d_in[10];
    const float* rmean = (const float*)d_in[11];
    const float* rvar  = (const float*)d_in[12];
    float* out = (float*)d_out;

    (void)in_sizes; (void)n_in; (void)out_size;

    const int smem_k3 = (75 * ZS + 75 * AS + 128) * (int)sizeof(float);
    cudaFuncSetAttribute(k_out2, cudaFuncAttributeMaxDynamicSharedMemorySize, smem_k3);

    k_mm<<<dim3(59, 64, 3), 256>>>(x, Wa, ba, Wb, bb, Wg);
    k_attn<<<192, 256>>>(Ast, Gat);
    k_out2<<<dim3(75, 64), 320, smem_k3>>>(x, bg, gamma, beta, rmean, rvar, out);
}

// round 9
// speedup vs baseline: 1.5107x; 1.1470x over previous
#include <cuda_runtime.h>
#include <math.h>

// Problem constants (fixed shapes)
#define NB   64      // batch N
#define CIN  64      // in channels C
#define TT   300     // time T
#define VV   25      // vertices V
#define TVN  7500    // T*V
#define CI   16      // inter channels
#define CO   64      // out channels
#define NS   3       // subsets
#define KCT  4800    // CI*T

typedef unsigned long long u64;

// f32x2 helpers (FFMA2 — PTX-only on sm_103a)
__device__ __forceinline__ u64 pk2(float lo, float hi) {
    u64 r;
    asm("mov.b64 %0, {%1, %2};" : "=l"(r)
        : "r"(__float_as_uint(lo)), "r"(__float_as_uint(hi)));
    return r;
}
__device__ __forceinline__ void fma2(u64& d, u64 a, u64 b) {
    asm("fma.rn.f32x2 %0, %1, %2, %0;" : "+l"(d) : "l"(a), "l"(b));
}
__device__ __forceinline__ float2 upk(u64 a) {
    unsigned int lo, hi;
    asm("mov.b64 {%0, %1}, %2;" : "=r"(lo), "=r"(hi) : "l"(a));
    return make_float2(__uint_as_float(lo), __uint_as_float(hi));
}

// Scratch (device globals; allocation is forbidden)
__device__ float g_a[(size_t)NS * NB * CI * TVN];   // per-(s,n) 4800x25 row-major
__device__ float g_b[(size_t)NS * NB * CI * TVN];
__device__ float g_z[(size_t)NS * NB * CO * TVN];   // z_s = Wg_s @ x (no bias)
__device__ float g_attn[NS * NB * VV * VV];         // (s,n,u,v)

// ---------------------------------------------------------------------------
// Kernel 1 (k_mm): Out[96][7500] = W[96][64] @ X[64][7500] per (n, gz).
//   gz=0: rows 0..47 -> a = Wa@x (+ba), rows 48..95 -> b = Wb@x (+bb)
//   gz=1/2: z rows (gz-1)*96 .. +95 = Wg @ x (no bias)
// FFMA2 inner loop: row-pair accumulators, transposed W in smem (LDS.64 pairs),
// thread owns 4 consecutive columns (LDS.128 / LDG.128 / STG.128).
// ---------------------------------------------------------------------------
__global__ __launch_bounds__(256) void k_mm(
    const float* __restrict__ x,
    const float* __restrict__ Wa, const float* __restrict__ ba,
    const float* __restrict__ Wb, const float* __restrict__ bb,
    const float* __restrict__ Wg)
{
    __shared__ float Wt[64][100];     // Wt[k][r] (transposed), 25.6 KB
    __shared__ float Xsm[32][128];    // 16 KB

    const int n    = blockIdx.y;
    const int col0 = blockIdx.x * 128;
    const int gz   = blockIdx.z;
    const int tid  = threadIdx.x;

    for (int idx = tid; idx < 96 * 64; idx += 256) {
        int r = idx >> 6, k = idx & 63;
        float w;
        if (gz == 0) w = (r < 48) ? Wa[r * 64 + k] : Wb[(r - 48) * 64 + k];
        else         w = Wg[((gz - 1) * 96 + r) * 64 + k];
        Wt[k][r] = w;
    }

    const int tx = tid & 31, ty = tid >> 5;
    const int r0 = ty * 12;           // 12 rows per thread (6 pairs)
    const int c4 = tx * 4;            // 4 consecutive cols per thread

    u64 acc[6][4];
#pragma unroll
    for (int p = 0; p < 6; p++)
#pragma unroll
        for (int q = 0; q < 4; q++) acc[p][q] = 0ull;

    const float* xb = x + (size_t)n * CIN * TVN;

    for (int kc = 0; kc < 2; kc++) {
        __syncthreads();
        // fill Xsm: 1024 float4s, 4 per thread
        for (int idx = tid; idx < 1024; idx += 256) {
            int c = idx >> 5, cc4 = (idx & 31) * 4;
            int col = col0 + cc4;
            float4 v = make_float4(0.f, 0.f, 0.f, 0.f);
            if (col < TVN)  // 7500 % 4 == 0, so whole float4 in range
                v = *reinterpret_cast<const float4*>(
                        &xb[(size_t)(kc * 32 + c) * TVN + col]);
            *reinterpret_cast<float4*>(&Xsm[c][cc4]) = v;
        }
        __syncthreads();
#pragma unroll 8
        for (int kk = 0; kk < 32; kk++) {
            const float* wrow = &Wt[kc * 32 + kk][r0];
            u64 w01 = *reinterpret_cast<const u64*>(wrow + 0);
            u64 w23 = *reinterpret_cast<const u64*>(wrow + 2);
            u64 w45 = *reinterpret_cast<const u64*>(wrow + 4);
            u64 w67 = *reinterpret_cast<const u64*>(wrow + 6);
            u64 w89 = *reinterpret_cast<const u64*>(wrow + 8);
            u64 wAB = *reinterpret_cast<const u64*>(wrow + 10);
            float4 xq = *reinterpret_cast<const float4*>(&Xsm[kk][c4]);
            u64 xd[4];
            xd[0] = pk2(xq.x, xq.x); xd[1] = pk2(xq.y, xq.y);
            xd[2] = pk2(xq.z, xq.z); xd[3] = pk2(xq.w, xq.w);
#pragma unroll
            for (int q = 0; q < 4; q++) {
                fma2(acc[0][q], w01, xd[q]);
                fma2(acc[1][q], w23, xd[q]);
                fma2(acc[2][q], w45, xd[q]);
                fma2(acc[3][q], w67, xd[q]);
                fma2(acc[4][q], w89, xd[q]);
                fma2(acc[5][q], wAB, xd[q]);
            }
        }
    }

    // epilogue: unpack pairs, add bias, STG.128 per row
    const int col = col0 + c4;
    if (col < TVN) {
#pragma unroll
        for (int p = 0; p < 6; p++) {
            float2 f0 = upk(acc[p][0]);
            float2 f1 = upk(acc[p][1]);
            float2 f2 = upk(acc[p][2]);
            float2 f3 = upk(acc[p][3]);
#pragma unroll
            for (int h = 0; h < 2; h++) {
                int r = r0 + 2 * p + h;
                float* dst;
                float bias;
                if (gz == 0) {
                    int which = (r >= 48);
                    int rr = which ? r - 48 : r;       // s*16 + ci
                    bias = which ? bb[rr] : ba[rr];
                    int s = rr >> 4, ci = rr & 15;
                    dst = (which ? g_b : g_a) + ((size_t)(s * NB + n) * CI + ci) * TVN;
                } else {
                    int zr = (gz - 1) * 96 + r;        // s*64 + o
                    int s = zr >> 6, o = zr & 63;
                    bias = 0.f;
                    dst = g_z + ((size_t)(s * NB + n) * CO + o) * TVN;
                }
                float4 outv;
                outv.x = (h ? f0.y : f0.x) + bias;
                outv.y = (h ? f1.y : f1.x) + bias;
                outv.z = (h ? f2.y : f2.x) + bias;
                outv.w = (h ? f3.y : f3.x) + bias;
                *reinterpret_cast<float4*>(&dst[col]) = outv;
            }
        }
    }
}

// ---------------------------------------------------------------------------
// Kernel 2: per (s,n): G[u,v] = (1/4800) * sum_k a[k,u]*b[k,v]  (k = ci*T+t)
// then softmax over u (axis -2), + (A_static + graph_attn), store attn.
// ---------------------------------------------------------------------------
__global__ __launch_bounds__(256) void k_attn(
    const float* __restrict__ Ast, const float* __restrict__ Gat)
{
    const int sn = blockIdx.x;          // s*64 + n
    const int s  = sn >> 6;
    const float* Abase = g_a + (size_t)sn * (CI * TVN);
    const float* Bbase = g_b + (size_t)sn * (CI * TVN);

    __shared__ float at[32 * 25];
    __shared__ float bt[32 * 25];
    __shared__ float Gsm[625];

    const int tid = threadIdx.x;
    const int u   = tid / 5;
    const int v0  = (tid % 5) * 5;
    const bool act = (tid < 125);

    float acc[5] = {0.f, 0.f, 0.f, 0.f, 0.f};

    float pa[4], pb[4];
#pragma unroll
    for (int q = 0; q < 4; q++) {
        int idx = tid + 256 * q;
        if (idx < 800) { pa[q] = Abase[idx]; pb[q] = Bbase[idx]; }
    }

    for (int kc = 0; kc < 150; kc++) {
        __syncthreads();
#pragma unroll
        for (int q = 0; q < 4; q++) {
            int idx = tid + 256 * q;
            if (idx < 800) { at[idx] = pa[q]; bt[idx] = pb[q]; }
        }
        __syncthreads();
        if (kc < 149) {
            const float* An = Abase + (kc + 1) * 800;
            const float* Bn = Bbase + (kc + 1) * 800;
#pragma unroll
            for (int q = 0; q < 4; q++) {
                int idx = tid + 256 * q;
                if (idx < 800) { pa[q] = An[idx]; pb[q] = Bn[idx]; }
            }
        }
        if (act) {
#pragma unroll 8
            for (int kk = 0; kk < 32; kk++) {
                float av = at[kk * 25 + u];
#pragma unroll
                for (int j = 0; j < 5; j++)
                    acc[j] = fmaf(av, bt[kk * 25 + v0 + j], acc[j]);
            }
        }
    }

    __syncthreads();
    if (act) {
#pragma unroll
        for (int j = 0; j < 5; j++)
            Gsm[u * 25 + v0 + j] = acc[j] * (1.0f / 4800.0f);
    }
    __syncthreads();

    if (tid < 25) {
        const int v = tid;
        float m = -INFINITY;
        for (int uu = 0; uu < 25; uu++) m = fmaxf(m, Gsm[uu * 25 + v]);
        float ssum = 0.f;
        for (int uu = 0; uu < 25; uu++) {
            float e = expf(Gsm[uu * 25 + v] - m);
            Gsm[uu * 25 + v] = e;
            ssum += e;
        }
        float sinv = 1.0f / ssum;
        float* dst = g_attn + (size_t)sn * 625;
        const float* a1 = Ast + s * 625;
        const float* a2 = Gat + s * 625;
        for (int uu = 0; uu < 25; uu++) {
            int i = uu * 25 + v;
            dst[i] = Gsm[i] * sinv + a1[i] + a2[i];
        }
    }
}

// ---------------------------------------------------------------------------
// Kernel 3 (k_out2): out[o,t,v] = relu( BN( sum_{s,u} z[s,o,t,u]*attn[s,u,v]
//                                         + sum_s bg[s,o] ) + x )
// K = 75 (s,u). Block = (n, 4-t tile), 320 threads. FFMA2 over o-row-pairs.
// ---------------------------------------------------------------------------
#define ZS 260    // zsm row stride (mult of 4 for alignment)
#define AS 26     // attn row stride

__global__ __launch_bounds__(320) void k_out2(
    const float* __restrict__ x,
    const float* __restrict__ bg,
    const float* __restrict__ gamma, const float* __restrict__ beta,
    const float* __restrict__ rmean, const float* __restrict__ rvar,
    float* __restrict__ out)
{
    extern __shared__ float sm[];
    float* zsm = sm;                   // 75*260 = 19500
    float* atn = zsm + 75 * ZS;        // 75*26  = 1950
    float* sc  = atn + 75 * AS;        // 64
    float* sh  = sc + 64;              // 64

    const int n   = blockIdx.y;
    const int t0  = blockIdx.x * 4;
    const int tid = threadIdx.x;

    // attn -> smem, keyed by k = s*25+u
    for (int idx = tid; idx < 1875; idx += 320) {
        int s = idx / 625, rem = idx - s * 625;    // rem = u*25+v
        int u = rem / 25, v = rem - u * 25;
        atn[(s * 25 + u) * AS + v] = g_attn[(size_t)(s * NB + n) * 625 + rem];
    }
    // z -> smem transposed: zsm[s*25+u][tt*64+o]
    for (int idx = tid; idx < 19200; idx += 320) {
        int seg = idx / 100, pos = idx - seg * 100;   // seg = s*64+o, pos = tt*25+u
        int s = seg >> 6, o = seg & 63;
        int tt = pos / 25, u = pos - tt * 25;
        zsm[(s * 25 + u) * ZS + tt * 64 + o] =
            g_z[((size_t)(s * NB + n) * CO + o) * TVN + t0 * 25 + pos];
    }
    if (tid < 64) {
        float inv = rsqrtf(rvar[tid] + 1e-5f);
        float s0 = gamma[tid] * inv;
        float bsum = bg[tid] + bg[64 + tid] + bg[128 + tid];
        sc[tid] = s0;
        sh[tid] = beta[tid] + (bsum - rmean[tid]) * s0;
    }
    __syncthreads();

    const int rg = tid / 5, cg = tid - rg * 5;
    const int r0 = rg * 4, v0 = cg * 5;
    const int t  = r0 >> 6, o0 = r0 & 63;

    u64 a2[2][5];
#pragma unroll
    for (int i = 0; i < 2; i++)
#pragma unroll
        for (int j = 0; j < 5; j++) a2[i][j] = 0ull;

#pragma unroll 5
    for (int k = 0; k < 75; k++) {
        const float* zr = &zsm[k * ZS + r0];
        u64 z01 = *reinterpret_cast<const u64*>(zr + 0);
        u64 z23 = *reinterpret_cast<const u64*>(zr + 2);
#pragma unroll
        for (int j = 0; j < 5; j++) {
            float av = atn[k * AS + v0 + j];
            u64 ad = pk2(av, av);
            fma2(a2[0][j], z01, ad);
            fma2(a2[1][j], z23, ad);
        }
    }

    // epilogue: BN + bias-sum + residual + relu, straight to global
    const float* xb = x + (size_t)n * CIN * TVN;
    float* ob = out + (size_t)n * CIN * TVN;
#pragma unroll
    for (int i = 0; i < 4; i++) {
        int o = o0 + i;
        size_t base = (size_t)o * TVN + (t0 + t) * 25 + v0;
        float s0 = sc[o], h0 = sh[o];
#pragma unroll
        for (int j = 0; j < 5; j++) {
            float2 f = upk(a2[i >> 1][j]);
            float a = (i & 1) ? f.y : f.x;
            float val = a * s0 + h0 + xb[base + j];
            ob[base + j] = fmaxf(val, 0.f);
        }
    }
}

// ---------------------------------------------------------------------------
extern "C" void kernel_launch(void* const* d_in, const int* in_sizes, int n_in,
                              void* d_out, int out_size)
{
    const float* x     = (const float*)d_in[0];
    const float* Ast   = (const float*)d_in[1];
    const float* Gat   = (const float*)d_in[2];
    const float* Wg    = (const float*)d_in[3];
    const float* bg    = (const float*)d_in[4];
    const float* Wa    = (const float*)d_in[5];
    const float* ba    = (const float*)d_in[6];
    const float* Wb    = (const float*)d_in[7];
    const float* bb    = (const float*)d_in[8];
    const float* gamma = (const float*)d_in[9];
    const float* beta  = (const float*)d_in[10];
    const float* rmean = (const float*)d_in[11];
    const float* rvar  = (const float*)d_in[12];
    float* out = (float*)d_out;

    (void)in_sizes; (void)n_in; (void)out_size;

    const int smem_k3 = (75 * ZS + 75 * AS + 128) * (int)sizeof(float);
    cudaFuncSetAttribute(k_out2, cudaFuncAttributeMaxDynamicSharedMemorySize, smem_k3);

    k_mm<<<dim3(59, 64, 3), 256>>>(x, Wa, ba, Wb, bb, Wg);
    k_attn<<<192, 256>>>(Ast, Gat);
    k_out2<<<dim3(75, 64), 320, smem_k3>>>(x, bg, gamma, beta, rmean, rvar, out);
}

// round 12
// speedup vs baseline: 1.7520x; 1.1597x over previous
#include <cuda_runtime.h>
#include <math.h>

// Problem constants (fixed shapes)
#define NB   64      // batch N
#define CIN  64      // in channels C
#define TT   300     // time T
#define VV   25      // vertices V
#define TVN  7500    // T*V
#define CI   16      // inter channels
#define CO   64      // out channels
#define NS   3       // subsets
#define KCT  4800    // CI*T

typedef unsigned long long u64;

// f32x2 helpers (FFMA2 — PTX-only on sm_103a)
__device__ __forceinline__ u64 pk2(float lo, float hi) {
    u64 r;
    asm("mov.b64 %0, {%1, %2};" : "=l"(r)
        : "r"(__float_as_uint(lo)), "r"(__float_as_uint(hi)));
    return r;
}
__device__ __forceinline__ void fma2(u64& d, u64 a, u64 b) {
    asm("fma.rn.f32x2 %0, %1, %2, %0;" : "+l"(d) : "l"(a), "l"(b));
}
__device__ __forceinline__ float2 upk(u64 a) {
    unsigned int lo, hi;
    asm("mov.b64 {%0, %1}, %2;" : "=r"(lo), "=r"(hi) : "l"(a));
    return make_float2(__uint_as_float(lo), __uint_as_float(hi));
}

// Scratch (device globals; allocation is forbidden)
__device__ float g_a[(size_t)NS * NB * CI * TVN];   // per-(s,n) 4800x25 row-major
__device__ float g_b[(size_t)NS * NB * CI * TVN];
__device__ float g_z[(size_t)NS * NB * CO * TVN];   // z_s = Wg_s @ x (no bias)
__device__ float g_attn[NS * NB * VV * VV];         // (s,n,u,v)

// ---------------------------------------------------------------------------
// Kernel 1 (k_mm): Out[96][7500] = W[96][64] @ X[64][7500] per (n, gz).
//   gz=0: rows 0..47 -> a = Wa@x (+ba), rows 48..95 -> b = Wb@x (+bb)
//   gz=1/2: z rows (gz-1)*96 .. +95 = Wg @ x (no bias)
// 384 threads: 12 warps x 8 rows (4 FFMA2 row-pairs) x 4 cols.
// Register-prefetch double-buffer on the X chunk hides DRAM latency.
// ---------------------------------------------------------------------------
__global__ __launch_bounds__(384) void k_mm(
    const float* __restrict__ x,
    const float* __restrict__ Wa, const float* __restrict__ ba,
    const float* __restrict__ Wb, const float* __restrict__ bb,
    const float* __restrict__ Wg)
{
    __shared__ float Wt[64][100];     // Wt[k][r] (transposed), 25.6 KB
    __shared__ float Xsm[32][128];    // 16 KB

    const int n    = blockIdx.y;
    const int col0 = blockIdx.x * 128;
    const int gz   = blockIdx.z;
    const int tid  = threadIdx.x;

    for (int idx = tid; idx < 96 * 64; idx += 384) {
        int r = idx >> 6, k = idx & 63;
        float w;
        if (gz == 0) w = (r < 48) ? Wa[r * 64 + k] : Wb[(r - 48) * 64 + k];
        else         w = Wg[((gz - 1) * 96 + r) * 64 + k];
        Wt[k][r] = w;
    }

    const int tx = tid & 31, ty = tid >> 5;   // ty 0..11
    const int r0 = ty * 8;            // 8 rows per thread (4 pairs)
    const int c4 = tx * 4;            // 4 consecutive cols per thread

    u64 acc[4][4];
#pragma unroll
    for (int p = 0; p < 4; p++)
#pragma unroll
        for (int q = 0; q < 4; q++) acc[p][q] = 0ull;

    const float* xb = x + (size_t)n * CIN * TVN;

    // prefetch chunk 0 into registers (1024 float4s, <=3 per thread)
    float4 px[3];
#pragma unroll
    for (int i = 0; i < 3; i++) {
        int idx = tid + 384 * i;
        if (idx < 1024) {
            int c = idx >> 5, cc4 = (idx & 31) * 4;
            int col = col0 + cc4;
            px[i] = make_float4(0.f, 0.f, 0.f, 0.f);
            if (col < TVN)
                px[i] = *reinterpret_cast<const float4*>(&xb[(size_t)c * TVN + col]);
        }
    }

    for (int kc = 0; kc < 2; kc++) {
        if (kc > 0) __syncthreads();          // protect Xsm overwrite
#pragma unroll
        for (int i = 0; i < 3; i++) {
            int idx = tid + 384 * i;
            if (idx < 1024) {
                int c = idx >> 5, cc4 = (idx & 31) * 4;
                *reinterpret_cast<float4*>(&Xsm[c][cc4]) = px[i];
            }
        }
        __syncthreads();                      // Xsm (and Wt on kc=0) visible
        if (kc == 0) {                        // prefetch chunk 1 behind compute
#pragma unroll
            for (int i = 0; i < 3; i++) {
                int idx = tid + 384 * i;
                if (idx < 1024) {
                    int c = idx >> 5, cc4 = (idx & 31) * 4;
                    int col = col0 + cc4;
                    px[i] = make_float4(0.f, 0.f, 0.f, 0.f);
                    if (col < TVN)
                        px[i] = *reinterpret_cast<const float4*>(
                                    &xb[(size_t)(32 + c) * TVN + col]);
                }
            }
        }
#pragma unroll 8
        for (int kk = 0; kk < 32; kk++) {
            const float* wrow = &Wt[kc * 32 + kk][r0];
            u64 w01 = *reinterpret_cast<const u64*>(wrow + 0);
            u64 w23 = *reinterpret_cast<const u64*>(wrow + 2);
            u64 w45 = *reinterpret_cast<const u64*>(wrow + 4);
            u64 w67 = *reinterpret_cast<const u64*>(wrow + 6);
            float4 xq = *reinterpret_cast<const float4*>(&Xsm[kk][c4]);
            u64 xd[4];
            xd[0] = pk2(xq.x, xq.x); xd[1] = pk2(xq.y, xq.y);
            xd[2] = pk2(xq.z, xq.z); xd[3] = pk2(xq.w, xq.w);
#pragma unroll
            for (int q = 0; q < 4; q++) {
                fma2(acc[0][q], w01, xd[q]);
                fma2(acc[1][q], w23, xd[q]);
                fma2(acc[2][q], w45, xd[q]);
                fma2(acc[3][q], w67, xd[q]);
            }
        }
    }

    // epilogue: unpack pairs, add bias, STG.128 per row
    const int col = col0 + c4;
    if (col < TVN) {
#pragma unroll
        for (int p = 0; p < 4; p++) {
            float2 f0 = upk(acc[p][0]);
            float2 f1 = upk(acc[p][1]);
            float2 f2 = upk(acc[p][2]);
            float2 f3 = upk(acc[p][3]);
#pragma unroll
            for (int h = 0; h < 2; h++) {
                int r = r0 + 2 * p + h;
                float* dst;
                float bias;
                if (gz == 0) {
                    int which = (r >= 48);
                    int rr = which ? r - 48 : r;       // s*16 + ci
                    bias = which ? bb[rr] : ba[rr];
                    int s = rr >> 4, ci = rr & 15;
                    dst = (which ? g_b : g_a) + ((size_t)(s * NB + n) * CI + ci) * TVN;
                } else {
                    int zr = (gz - 1) * 96 + r;        // s*64 + o
                    int s = zr >> 6, o = zr & 63;
                    bias = 0.f;
                    dst = g_z + ((size_t)(s * NB + n) * CO + o) * TVN;
                }
                float4 outv;
                outv.x = (h ? f0.y : f0.x) + bias;
                outv.y = (h ? f1.y : f1.x) + bias;
                outv.z = (h ? f2.y : f2.x) + bias;
                outv.w = (h ? f3.y : f3.x) + bias;
                *reinterpret_cast<float4*>(&dst[col]) = outv;
            }
        }
    }
}

// ---------------------------------------------------------------------------
// Kernel 2: per (s,n): G[u,v] = (1/4800) * sum_k a[k,u]*b[k,v]  (k = ci*T+t)
// then softmax over u (axis -2), + (A_static + graph_attn), store attn.
// ---------------------------------------------------------------------------
__global__ __launch_bounds__(256) void k_attn(
    const float* __restrict__ Ast, const float* __restrict__ Gat)
{
    const int sn = blockIdx.x;          // s*64 + n
    const int s  = sn >> 6;
    const float* Abase = g_a + (size_t)sn * (CI * TVN);
    const float* Bbase = g_b + (size_t)sn * (CI * TVN);

    __shared__ float at[32 * 25];
    __shared__ float bt[32 * 25];
    __shared__ float Gsm[625];

    const int tid = threadIdx.x;
    const int u   = tid / 5;
    const int v0  = (tid % 5) * 5;
    const bool act = (tid < 125);

    float acc[5] = {0.f, 0.f, 0.f, 0.f, 0.f};

    float pa[4], pb[4];
#pragma unroll
    for (int q = 0; q < 4; q++) {
        int idx = tid + 256 * q;
        if (idx < 800) { pa[q] = Abase[idx]; pb[q] = Bbase[idx]; }
    }

    for (int kc = 0; kc < 150; kc++) {
        __syncthreads();
#pragma unroll
        for (int q = 0; q < 4; q++) {
            int idx = tid + 256 * q;
            if (idx < 800) { at[idx] = pa[q]; bt[idx] = pb[q]; }
        }
        __syncthreads();
        if (kc < 149) {
            const float* An = Abase + (kc + 1) * 800;
            const float* Bn = Bbase + (kc + 1) * 800;
#pragma unroll
            for (int q = 0; q < 4; q++) {
                int idx = tid + 256 * q;
                if (idx < 800) { pa[q] = An[idx]; pb[q] = Bn[idx]; }
            }
        }
        if (act) {
#pragma unroll 8
            for (int kk = 0; kk < 32; kk++) {
                float av = at[kk * 25 + u];
#pragma unroll
                for (int j = 0; j < 5; j++)
                    acc[j] = fmaf(av, bt[kk * 25 + v0 + j], acc[j]);
            }
        }
    }

    __syncthreads();
    if (act) {
#pragma unroll
        for (int j = 0; j < 5; j++)
            Gsm[u * 25 + v0 + j] = acc[j] * (1.0f / 4800.0f);
    }
    __syncthreads();

    if (tid < 25) {
        const int v = tid;
        float m = -INFINITY;
        for (int uu = 0; uu < 25; uu++) m = fmaxf(m, Gsm[uu * 25 + v]);
        float ssum = 0.f;
        for (int uu = 0; uu < 25; uu++) {
            float e = expf(Gsm[uu * 25 + v] - m);
            Gsm[uu * 25 + v] = e;
            ssum += e;
        }
        float sinv = 1.0f / ssum;
        float* dst = g_attn + (size_t)sn * 625;
        const float* a1 = Ast + s * 625;
        const float* a2 = Gat + s * 625;
        for (int uu = 0; uu < 25; uu++) {
            int i = uu * 25 + v;
            dst[i] = Gsm[i] * sinv + a1[i] + a2[i];
        }
    }
}

// ---------------------------------------------------------------------------
// Kernel 3 (k_out2): out[o,t,v] = relu( BN( sum_{s,u} z[s,o,t,u]*attn[s,u,v]
//                                         + sum_s bg[s,o] ) + x )
// K = 75 (s,u). Block = (n, 4-t tile), 320 threads. FFMA2 over o-row-pairs.
// z loaded from global as float4 (LDG.128), scattered into transposed zsm.
// ---------------------------------------------------------------------------
#define ZS 260    // zsm row stride (mult of 4 for alignment)
#define AS 26     // attn row stride

__global__ __launch_bounds__(320) void k_out2(
    const float* __restrict__ x,
    const float* __restrict__ bg,
    const float* __restrict__ gamma, const float* __restrict__ beta,
    const float* __restrict__ rmean, const float* __restrict__ rvar,
    float* __restrict__ out)
{
    extern __shared__ float sm[];
    float* zsm = sm;                   // 75*260 = 19500
    float* atn = zsm + 75 * ZS;        // 75*26  = 1950
    float* sc  = atn + 75 * AS;        // 64
    float* sh  = sc + 64;              // 64

    const int n   = blockIdx.y;
    const int t0  = blockIdx.x * 4;
    const int tid = threadIdx.x;

    // attn -> smem, keyed by k = s*25+u
    for (int idx = tid; idx < 1875; idx += 320) {
        int s = idx / 625, rem = idx - s * 625;    // rem = u*25+v
        int u = rem / 25, v = rem - u * 25;
        atn[(s * 25 + u) * AS + v] = g_attn[(size_t)(s * NB + n) * 625 + rem];
    }
    // z -> smem transposed: zsm[s*25+u][tt*64+o], via float4 global loads
    for (int fidx = tid; fidx < 4800; fidx += 320) {
        int seg = fidx / 25, f = fidx - seg * 25;     // seg = s*64+o, f = float4 idx
        int s = seg >> 6, o = seg & 63;
        float4 v = *reinterpret_cast<const float4*>(
            &g_z[((size_t)(s * NB + n) * CO + o) * TVN + t0 * 25 + f * 4]);
        const float* vp = reinterpret_cast<const float*>(&v);
#pragma unroll
        for (int j = 0; j < 4; j++) {
            int pos = f * 4 + j;                      // pos = tt*25+u, < 100
            int tt = pos / 25, u = pos - tt * 25;
            zsm[(s * 25 + u) * ZS + tt * 64 + o] = vp[j];
        }
    }
    if (tid < 64) {
        float inv = rsqrtf(rvar[tid] + 1e-5f);
        float s0 = gamma[tid] * inv;
        float bsum = bg[tid] + bg[64 + tid] + bg[128 + tid];
        sc[tid] = s0;
        sh[tid] = beta[tid] + (bsum - rmean[tid]) * s0;
    }
    __syncthreads();

    const int rg = tid / 5, cg = tid - rg * 5;
    const int r0 = rg * 4, v0 = cg * 5;
    const int t  = r0 >> 6, o0 = r0 & 63;

    u64 a2[2][5];
#pragma unroll
    for (int i = 0; i < 2; i++)
#pragma unroll
        for (int j = 0; j < 5; j++) a2[i][j] = 0ull;

#pragma unroll 5
    for (int k = 0; k < 75; k++) {
        const float* zr = &zsm[k * ZS + r0];
        u64 z01 = *reinterpret_cast<const u64*>(zr + 0);
        u64 z23 = *reinterpret_cast<const u64*>(zr + 2);
#pragma unroll
        for (int j = 0; j < 5; j++) {
            float av = atn[k * AS + v0 + j];
            u64 ad = pk2(av, av);
            fma2(a2[0][j], z01, ad);
            fma2(a2[1][j], z23, ad);
        }
    }

    // epilogue: BN + bias-sum + residual + relu, straight to global
    const float* xb = x + (size_t)n * CIN * TVN;
    float* ob = out + (size_t)n * CIN * TVN;
#pragma unroll
    for (int i = 0; i < 4; i++) {
        int o = o0 + i;
        size_t base = (size_t)o * TVN + (t0 + t) * 25 + v0;
        float s0 = sc[o], h0 = sh[o];
#pragma unroll
        for (int j = 0; j < 5; j++) {
            float2 f = upk(a2[i >> 1][j]);
            float a = (i & 1) ? f.y : f.x;
            float val = a * s0 + h0 + xb[base + j];
            ob[base + j] = fmaxf(val, 0.f);
        }
    }
}

// ---------------------------------------------------------------------------
extern "C" void kernel_launch(void* const* d_in, const int* in_sizes, int n_in,
                              void* d_out, int out_size)
{
    const float* x     = (const float*)d_in[0];
    const float* Ast   = (const float*)d_in[1];
    const float* Gat   = (const float*)d_in[2];
    const float* Wg    = (const float*)d_in[3];
    const float* bg    = (const float*)d_in[4];
    const float* Wa    = (const float*)d_in[5];
    const float* ba    = (const float*)d_in[6];
    const float* Wb    = (const float*)d_in[7];
    const float* bb    = (const float*)d_in[8];
    const float* gamma = (const float*)d_in[9];
    const float* beta  = (const float*)d_in[10];
    const float* rmean = (const float*)d_in[11];
    const float* rvar  = (const float*)d_in[12];
    float* out = (float*)d_out;

    (void)in_sizes; (void)n_in; (void)out_size;

    const int smem_k3 = (75 * ZS + 75 * AS + 128) * (int)sizeof(float);
    cudaFuncSetAttribute(k_out2, cudaFuncAttributeMaxDynamicSharedMemorySize, smem_k3);

    k_mm<<<dim3(59, 64, 3), 384>>>(x, Wa, ba, Wb, bb, Wg);
    k_attn<<<192, 256>>>(Ast, Gat);
    k_out2<<<dim3(75, 64), 320, smem_k3>>>(x, bg, gamma, beta, rmean, rvar, out);
}

// round 13
// speedup vs baseline: 1.8345x; 1.0471x over previous
#include <cuda_runtime.h>
#include <cuda_bf16.h>
#include <math.h>

// Problem constants (fixed shapes)
#define NB   64      // batch N
#define CIN  64      // in channels C
#define TT   300     // time T
#define VV   25      // vertices V
#define TVN  7500    // T*V
#define CI   16      // inter channels
#define CO   64      // out channels
#define NS   3       // subsets
#define KCT  4800    // CI*T
#define SPLITS 6     // k_attn split-K factor (4800/6 = 800)

typedef unsigned long long u64;

// f32x2 helpers (FFMA2 — PTX-only on sm_103a)
__device__ __forceinline__ u64 pk2(float lo, float hi) {
    u64 r;
    asm("mov.b64 %0, {%1, %2};" : "=l"(r)
        : "r"(__float_as_uint(lo)), "r"(__float_as_uint(hi)));
    return r;
}
__device__ __forceinline__ void fma2(u64& d, u64 a, u64 b) {
    asm("fma.rn.f32x2 %0, %1, %2, %0;" : "+l"(d) : "l"(a), "l"(b));
}
__device__ __forceinline__ float2 upk(u64 a) {
    unsigned int lo, hi;
    asm("mov.b64 {%0, %1}, %2;" : "=r"(lo), "=r"(hi) : "l"(a));
    return make_float2(__uint_as_float(lo), __uint_as_float(hi));
}

// Scratch (device globals; allocation is forbidden)
__device__ __nv_bfloat16 g_a[(size_t)NS * NB * CI * TVN];  // per-(s,n) 4800x25 row-major
__device__ __nv_bfloat16 g_b[(size_t)NS * NB * CI * TVN];
__device__ float g_z[(size_t)NS * NB * CO * TVN];          // z_s = Wg_s @ x (no bias)
__device__ float g_part[NS * NB * SPLITS * VV * VV];       // split-K partial logits
__device__ float g_attn[NS * NB * VV * VV];                // (s,n,u,v)

// ---------------------------------------------------------------------------
// Kernel 1 (k_mm): Out[96][7500] = W[96][64] @ X[64][7500] per (n, gz).
//   gz=0: rows 0..47 -> a = Wa@x (+ba), rows 48..95 -> b = Wb@x (+bb) [bf16 out]
//   gz=1/2: z rows (gz-1)*96 .. +95 = Wg @ x (no bias)               [fp32 out]
// 384 threads: 12 warps x 8 rows (4 FFMA2 row-pairs) x 4 cols.
// ---------------------------------------------------------------------------
__global__ __launch_bounds__(384) void k_mm(
    const float* __restrict__ x,
    const float* __restrict__ Wa, const float* __restrict__ ba,
    const float* __restrict__ Wb, const float* __restrict__ bb,
    const float* __restrict__ Wg)
{
    __shared__ float Wt[64][100];     // Wt[k][r] (transposed), 25.6 KB
    __shared__ float Xsm[32][128];    // 16 KB

    const int n    = blockIdx.y;
    const int col0 = blockIdx.x * 128;
    const int gz   = blockIdx.z;
    const int tid  = threadIdx.x;

    for (int idx = tid; idx < 96 * 64; idx += 384) {
        int r = idx >> 6, k = idx & 63;
        float w;
        if (gz == 0) w = (r < 48) ? Wa[r * 64 + k] : Wb[(r - 48) * 64 + k];
        else         w = Wg[((gz - 1) * 96 + r) * 64 + k];
        Wt[k][r] = w;
    }

    const int tx = tid & 31, ty = tid >> 5;   // ty 0..11
    const int r0 = ty * 8;            // 8 rows per thread (4 pairs)
    const int c4 = tx * 4;            // 4 consecutive cols per thread

    u64 acc[4][4];
#pragma unroll
    for (int p = 0; p < 4; p++)
#pragma unroll
        for (int q = 0; q < 4; q++) acc[p][q] = 0ull;

    const float* xb = x + (size_t)n * CIN * TVN;

    // prefetch chunk 0 into registers (1024 float4s, <=3 per thread)
    float4 px[3];
#pragma unroll
    for (int i = 0; i < 3; i++) {
        int idx = tid + 384 * i;
        if (idx < 1024) {
            int c = idx >> 5, cc4 = (idx & 31) * 4;
            int col = col0 + cc4;
            px[i] = make_float4(0.f, 0.f, 0.f, 0.f);
            if (col < TVN)
                px[i] = *reinterpret_cast<const float4*>(&xb[(size_t)c * TVN + col]);
        }
    }

    for (int kc = 0; kc < 2; kc++) {
        if (kc > 0) __syncthreads();          // protect Xsm overwrite
#pragma unroll
        for (int i = 0; i < 3; i++) {
            int idx = tid + 384 * i;
            if (idx < 1024) {
                int c = idx >> 5, cc4 = (idx & 31) * 4;
                *reinterpret_cast<float4*>(&Xsm[c][cc4]) = px[i];
            }
        }
        __syncthreads();                      // Xsm (and Wt on kc=0) visible
        if (kc == 0) {                        // prefetch chunk 1 behind compute
#pragma unroll
            for (int i = 0; i < 3; i++) {
                int idx = tid + 384 * i;
                if (idx < 1024) {
                    int c = idx >> 5, cc4 = (idx & 31) * 4;
                    int col = col0 + cc4;
                    px[i] = make_float4(0.f, 0.f, 0.f, 0.f);
                    if (col < TVN)
                        px[i] = *reinterpret_cast<const float4*>(
                                    &xb[(size_t)(32 + c) * TVN + col]);
                }
            }
        }
#pragma unroll 8
        for (int kk = 0; kk < 32; kk++) {
            const float* wrow = &Wt[kc * 32 + kk][r0];
            u64 w01 = *reinterpret_cast<const u64*>(wrow + 0);
            u64 w23 = *reinterpret_cast<const u64*>(wrow + 2);
            u64 w45 = *reinterpret_cast<const u64*>(wrow + 4);
            u64 w67 = *reinterpret_cast<const u64*>(wrow + 6);
            float4 xq = *reinterpret_cast<const float4*>(&Xsm[kk][c4]);
            u64 xd[4];
            xd[0] = pk2(xq.x, xq.x); xd[1] = pk2(xq.y, xq.y);
            xd[2] = pk2(xq.z, xq.z); xd[3] = pk2(xq.w, xq.w);
#pragma unroll
            for (int q = 0; q < 4; q++) {
                fma2(acc[0][q], w01, xd[q]);
                fma2(acc[1][q], w23, xd[q]);
                fma2(acc[2][q], w45, xd[q]);
                fma2(acc[3][q], w67, xd[q]);
            }
        }
    }

    // epilogue: unpack pairs, add bias, store (bf16 for a/b, fp32 for z)
    const int col = col0 + c4;
    if (col < TVN) {
#pragma unroll
        for (int p = 0; p < 4; p++) {
            float2 f0 = upk(acc[p][0]);
            float2 f1 = upk(acc[p][1]);
            float2 f2 = upk(acc[p][2]);
            float2 f3 = upk(acc[p][3]);
#pragma unroll
            for (int h = 0; h < 2; h++) {
                int r = r0 + 2 * p + h;
                float vx = (h ? f0.y : f0.x);
                float vy = (h ? f1.y : f1.x);
                float vz = (h ? f2.y : f2.x);
                float vw = (h ? f3.y : f3.x);
                if (gz == 0) {
                    int which = (r >= 48);
                    int rr = which ? r - 48 : r;       // s*16 + ci
                    float bias = which ? bb[rr] : ba[rr];
                    int s = rr >> 4, ci = rr & 15;
                    __nv_bfloat16* dst = (which ? g_b : g_a) +
                        ((size_t)(s * NB + n) * CI + ci) * TVN;
                    __nv_bfloat162 lo = __floats2bfloat162_rn(vx + bias, vy + bias);
                    __nv_bfloat162 hi = __floats2bfloat162_rn(vz + bias, vw + bias);
                    uint2 st;
                    st.x = *reinterpret_cast<unsigned int*>(&lo);
                    st.y = *reinterpret_cast<unsigned int*>(&hi);
                    *reinterpret_cast<uint2*>(dst + col) = st;
                } else {
                    int zr = (gz - 1) * 96 + r;        // s*64 + o
                    int s = zr >> 6, o = zr & 63;
                    float* dst = g_z + ((size_t)(s * NB + n) * CO + o) * TVN;
                    float4 outv = make_float4(vx, vy, vz, vw);
                    *reinterpret_cast<float4*>(&dst[col]) = outv;
                }
            }
        }
    }
}

// ---------------------------------------------------------------------------
// Kernel 2a (k_attn_p1): split-K partial logits.
// Block (sn, sp): k-range [sp*800, sp*800+800), 25 chunks of 32 k-rows.
// bf16 a/b loaded as uint4 (8 elems), converted to fp32 smem tiles.
// ---------------------------------------------------------------------------
__global__ __launch_bounds__(256) void k_attn_p1()
{
    const int sn = blockIdx.x;          // s*64 + n
    const int sp = blockIdx.y;
    const __nv_bfloat16* Ab = g_a + (size_t)sn * (CI * TVN) + sp * 20000;
    const __nv_bfloat16* Bb = g_b + (size_t)sn * (CI * TVN) + sp * 20000;

    __shared__ float at[800];
    __shared__ float bt[800];

    const int tid = threadIdx.x;
    const int u   = tid / 5;
    const int v0  = (tid % 5) * 5;
    const bool act = (tid < 125);
    const bool ld  = (tid < 200);
    const int arrb = (tid >= 100);
    const int j    = arrb ? tid - 100 : tid;   // uint4 index 0..99

    float acc[5] = {0.f, 0.f, 0.f, 0.f, 0.f};

    uint4 p;
    if (ld)
        p = reinterpret_cast<const uint4*>(arrb ? Bb : Ab)[j];

    for (int kc = 0; kc < 25; kc++) {
        __syncthreads();
        if (ld) {
            float* dstf = (arrb ? bt : at) + j * 8;
            float2 f0 = __bfloat1622float2(*reinterpret_cast<__nv_bfloat162*>(&p.x));
            float2 f1 = __bfloat1622float2(*reinterpret_cast<__nv_bfloat162*>(&p.y));
            float2 f2 = __bfloat1622float2(*reinterpret_cast<__nv_bfloat162*>(&p.z));
            float2 f3 = __bfloat1622float2(*reinterpret_cast<__nv_bfloat162*>(&p.w));
            *reinterpret_cast<float2*>(dstf + 0) = f0;
            *reinterpret_cast<float2*>(dstf + 2) = f1;
            *reinterpret_cast<float2*>(dstf + 4) = f2;
            *reinterpret_cast<float2*>(dstf + 6) = f3;
        }
        __syncthreads();
        if (kc < 24 && ld)
            p = reinterpret_cast<const uint4*>((arrb ? Bb : Ab) + (kc + 1) * 800)[j];
        if (act) {
#pragma unroll 8
            for (int kk = 0; kk < 32; kk++) {
                float av = at[kk * 25 + u];
#pragma unroll
                for (int jj = 0; jj < 5; jj++)
                    acc[jj] = fmaf(av, bt[kk * 25 + v0 + jj], acc[jj]);
            }
        }
    }

    if (act) {
        float* dst = g_part + ((size_t)sn * SPLITS + sp) * 625 + u * 25 + v0;
#pragma unroll
        for (int jj = 0; jj < 5; jj++) dst[jj] = acc[jj];
    }
}

// ---------------------------------------------------------------------------
// Kernel 2b (k_attn_p2): reduce partials, softmax over u, + (Ast+Gat), store.
// ---------------------------------------------------------------------------
__global__ __launch_bounds__(128) void k_attn_p2(
    const float* __restrict__ Ast, const float* __restrict__ Gat)
{
    const int sn = blockIdx.x;
    const int s  = sn >> 6;
    __shared__ float Gsm[625];
    const int tid = threadIdx.x;

    if (tid < 125) {
        int u = tid / 5, v0 = (tid % 5) * 5;
#pragma unroll
        for (int jj = 0; jj < 5; jj++) {
            float sum = 0.f;
#pragma unroll
            for (int sp = 0; sp < SPLITS; sp++)
                sum += g_part[((size_t)sn * SPLITS + sp) * 625 + u * 25 + v0 + jj];
            Gsm[u * 25 + v0 + jj] = sum * (1.0f / 4800.0f);
        }
    }
    __syncthreads();

    if (tid < 25) {
        const int v = tid;
        float m = -INFINITY;
        for (int uu = 0; uu < 25; uu++) m = fmaxf(m, Gsm[uu * 25 + v]);
        float ssum = 0.f;
        for (int uu = 0; uu < 25; uu++) {
            float e = expf(Gsm[uu * 25 + v] - m);
            Gsm[uu * 25 + v] = e;
            ssum += e;
        }
        float sinv = 1.0f / ssum;
        float* dst = g_attn + (size_t)sn * 625;
        const float* a1 = Ast + s * 625;
        const float* a2 = Gat + s * 625;
        for (int uu = 0; uu < 25; uu++) {
            int i = uu * 25 + v;
            dst[i] = Gsm[i] * sinv + a1[i] + a2[i];
        }
    }
}

// ---------------------------------------------------------------------------
// Kernel 3 (k_out2): out[o,t,v] = relu( BN( sum_{s,u} z[s,o,t,u]*attn[s,u,v]
//                                         + sum_s bg[s,o] ) + x )
// K = 75 (s,u). Block = (n, 4-t tile), 320 threads. FFMA2 over o-row-pairs.
// Epilogue: stage through smem, fully coalesced float4 x-read + out-write.
// ---------------------------------------------------------------------------
#define ZS 260    // zsm row stride (mult of 4 for alignment)
#define AS 26     // attn row stride

__global__ __launch_bounds__(320) void k_out2(
    const float* __restrict__ x,
    const float* __restrict__ bg,
    const float* __restrict__ gamma, const float* __restrict__ beta,
    const float* __restrict__ rmean, const float* __restrict__ rvar,
    float* __restrict__ out)
{
    extern __shared__ float sm[];
    float* zsm = sm;                   // 75*260 = 19500 (reused as osm later)
    float* atn = zsm + 75 * ZS;        // 75*26  = 1950
    float* sc  = atn + 75 * AS;        // 64
    float* sh  = sc + 64;              // 64
    float* osm = sm;                   // 64*100 = 6400 (after mainloop)

    const int n   = blockIdx.y;
    const int t0  = blockIdx.x * 4;
    const int tid = threadIdx.x;

    // attn -> smem, keyed by k = s*25+u
    for (int idx = tid; idx < 1875; idx += 320) {
        int s = idx / 625, rem = idx - s * 625;    // rem = u*25+v
        int u = rem / 25, v = rem - u * 25;
        atn[(s * 25 + u) * AS + v] = g_attn[(size_t)(s * NB + n) * 625 + rem];
    }
    // z -> smem transposed: zsm[s*25+u][tt*64+o], via float4 global loads
    for (int fidx = tid; fidx < 4800; fidx += 320) {
        int seg = fidx / 25, f = fidx - seg * 25;     // seg = s*64+o, f = float4 idx
        int s = seg >> 6, o = seg & 63;
        float4 v = *reinterpret_cast<const float4*>(
            &g_z[((size_t)(s * NB + n) * CO + o) * TVN + t0 * 25 + f * 4]);
        const float* vp = reinterpret_cast<const float*>(&v);
#pragma unroll
        for (int j = 0; j < 4; j++) {
            int pos = f * 4 + j;                      // pos = tt*25+u, < 100
            int tt = pos / 25, u = pos - tt * 25;
            zsm[(s * 25 + u) * ZS + tt * 64 + o] = vp[j];
        }
    }
    if (tid < 64) {
        float inv = rsqrtf(rvar[tid] + 1e-5f);
        float s0 = gamma[tid] * inv;
        float bsum = bg[tid] + bg[64 + tid] + bg[128 + tid];
        sc[tid] = s0;
        sh[tid] = beta[tid] + (bsum - rmean[tid]) * s0;
    }
    __syncthreads();

    const int rg = tid / 5, cg = tid - rg * 5;
    const int r0 = rg * 4, v0 = cg * 5;
    const int t  = r0 >> 6, o0 = r0 & 63;

    u64 a2[2][5];
#pragma unroll
    for (int i = 0; i < 2; i++)
#pragma unroll
        for (int j = 0; j < 5; j++) a2[i][j] = 0ull;

#pragma unroll 5
    for (int k = 0; k < 75; k++) {
        const float* zr = &zsm[k * ZS + r0];
        u64 z01 = *reinterpret_cast<const u64*>(zr + 0);
        u64 z23 = *reinterpret_cast<const u64*>(zr + 2);
#pragma unroll
        for (int j = 0; j < 5; j++) {
            float av = atn[k * AS + v0 + j];
            u64 ad = pk2(av, av);
            fma2(a2[0][j], z01, ad);
            fma2(a2[1][j], z23, ad);
        }
    }
    __syncthreads();   // all zsm reads done before osm overwrite

    // stage result tile into smem: osm[o][t*25+v]
#pragma unroll
    for (int i = 0; i < 4; i++) {
        int o = o0 + i;
#pragma unroll
        for (int j = 0; j < 5; j++) {
            float2 f = upk(a2[i >> 1][j]);
            osm[o * 100 + t * 25 + v0 + j] = (i & 1) ? f.y : f.x;
        }
    }
    __syncthreads();

    // coalesced epilogue: per o, the 100 cols are contiguous in gmem
    const float* xb = x + (size_t)n * CIN * TVN + (size_t)t0 * 25;
    float* ob = out + (size_t)n * CIN * TVN + (size_t)t0 * 25;
    for (int fidx = tid; fidx < 1600; fidx += 320) {
        int o = fidx / 25, f = fidx - o * 25;
        float4 r = *reinterpret_cast<const float4*>(&osm[o * 100 + f * 4]);
        float4 xv = *reinterpret_cast<const float4*>(&xb[(size_t)o * TVN + f * 4]);
        float s0 = sc[o], h0 = sh[o];
        float4 ov;
        ov.x = fmaxf(r.x * s0 + h0 + xv.x, 0.f);
        ov.y = fmaxf(r.y * s0 + h0 + xv.y, 0.f);
        ov.z = fmaxf(r.z * s0 + h0 + xv.z, 0.f);
        ov.w = fmaxf(r.w * s0 + h0 + xv.w, 0.f);
        *reinterpret_cast<float4*>(&ob[(size_t)o * TVN + f * 4]) = ov;
    }
}

// ---------------------------------------------------------------------------
extern "C" void kernel_launch(void* const* d_in, const int* in_sizes, int n_in,
                              void* d_out, int out_size)
{
    const float* x     = (const float*)d_in[0];
    const float* Ast   = (const float*)d_in[1];
    const float* Gat   = (const float*)d_in[2];
    const float* Wg    = (const float*)d_in[3];
    const float* bg    = (const float*)d_in[4];
    const float* Wa    = (const float*)d_in[5];
    const float* ba    = (const float*)d_in[6];
    const float* Wb    = (const float*)d_in[7];
    const float* bb    = (const float*)d_in[8];
    const float* gamma = (const float*)d_in[9];
    const float* beta  = (const float*)d_in[10];
    const float* rmean = (const float*)d_in[11];
    const float* rvar  = (const float*)d_in[12];
    float* out = (float*)d_out;

    (void)in_sizes; (void)n_in; (void)out_size;

    const int smem_k3 = (75 * ZS + 75 * AS + 128) * (int)sizeof(float);
    cudaFuncSetAttribute(k_out2, cudaFuncAttributeMaxDynamicSharedMemorySize, smem_k3);

    k_mm<<<dim3(59, 64, 3), 384>>>(x, Wa, ba, Wb, bb, Wg);
    k_attn_p1<<<dim3(192, SPLITS), 256>>>();
    k_attn_p2<<<192, 128>>>(Ast, Gat);
    k_out2<<<dim3(75, 64), 320, smem_k3>>>(x, bg, gamma, beta, rmean, rvar, out);
}

// round 14
// speedup vs baseline: 1.9276x; 1.0507x over previous
#include <cuda_runtime.h>
#include <cuda_bf16.h>
#include <math.h>

// Problem constants (fixed shapes)
#define NB   64      // batch N
#define CIN  64      // in channels C
#define TT   300     // time T
#define VV   25      // vertices V
#define TVN  7500    // T*V
#define CI   16      // inter channels
#define CO   64      // out channels
#define NS   3       // subsets
#define KCT  4800    // CI*T
#define SPLITS 6     // k_attn split-K factor (4800/6 = 800)

typedef unsigned long long u64;

// f32x2 helpers (FFMA2 — PTX-only on sm_103a)
__device__ __forceinline__ u64 pk2(float lo, float hi) {
    u64 r;
    asm("mov.b64 %0, {%1, %2};" : "=l"(r)
        : "r"(__float_as_uint(lo)), "r"(__float_as_uint(hi)));
    return r;
}
__device__ __forceinline__ void fma2(u64& d, u64 a, u64 b) {
    asm("fma.rn.f32x2 %0, %1, %2, %0;" : "+l"(d) : "l"(a), "l"(b));
}
__device__ __forceinline__ float2 upk(u64 a) {
    unsigned int lo, hi;
    asm("mov.b64 {%0, %1}, %2;" : "=r"(lo), "=r"(hi) : "l"(a));
    return make_float2(__uint_as_float(lo), __uint_as_float(hi));
}

// Scratch (device globals; allocation is forbidden)
__device__ __nv_bfloat16 g_a[(size_t)NS * NB * CI * TVN];  // per-(s,n) 4800x25 row-major
__device__ __nv_bfloat16 g_b[(size_t)NS * NB * CI * TVN];
__device__ float g_z[(size_t)NS * NB * CO * TVN];          // z_s = Wg_s @ x (no bias)
__device__ float g_part[NS * NB * SPLITS * VV * VV];       // split-K partial logits
__device__ float g_attn[NS * NB * VV * VV];                // (s,n,u,v)

// ---------------------------------------------------------------------------
// Kernel 1 (k_mm): Out[96][7500] = W[96][64] @ X[64][7500] per (n, gz).
//   gz=0: rows 0..47 -> a = Wa@x (+ba), rows 48..95 -> b = Wb@x (+bb) [bf16 out]
//   gz=1/2: z rows (gz-1)*96 .. +95 = Wg @ x (no bias)               [fp32 out]
// 384 threads: 12 warps x 8 rows (4 FFMA2 row-pairs) x 4 cols.
// ---------------------------------------------------------------------------
__global__ __launch_bounds__(384) void k_mm(
    const float* __restrict__ x,
    const float* __restrict__ Wa, const float* __restrict__ ba,
    const float* __restrict__ Wb, const float* __restrict__ bb,
    const float* __restrict__ Wg)
{
    __shared__ float Wt[64][100];     // Wt[k][r] (transposed), 25.6 KB
    __shared__ float Xsm[32][128];    // 16 KB

    const int n    = blockIdx.y;
    const int col0 = blockIdx.x * 128;
    const int gz   = blockIdx.z;
    const int tid  = threadIdx.x;

    for (int idx = tid; idx < 96 * 64; idx += 384) {
        int r = idx >> 6, k = idx & 63;
        float w;
        if (gz == 0) w = (r < 48) ? Wa[r * 64 + k] : Wb[(r - 48) * 64 + k];
        else         w = Wg[((gz - 1) * 96 + r) * 64 + k];
        Wt[k][r] = w;
    }

    const int tx = tid & 31, ty = tid >> 5;   // ty 0..11
    const int r0 = ty * 8;            // 8 rows per thread (4 pairs)
    const int c4 = tx * 4;            // 4 consecutive cols per thread

    u64 acc[4][4];
#pragma unroll
    for (int p = 0; p < 4; p++)
#pragma unroll
        for (int q = 0; q < 4; q++) acc[p][q] = 0ull;

    const float* xb = x + (size_t)n * CIN * TVN;

    // prefetch chunk 0 into registers (1024 float4s, <=3 per thread)
    float4 px[3];
#pragma unroll
    for (int i = 0; i < 3; i++) {
        int idx = tid + 384 * i;
        if (idx < 1024) {
            int c = idx >> 5, cc4 = (idx & 31) * 4;
            int col = col0 + cc4;
            px[i] = make_float4(0.f, 0.f, 0.f, 0.f);
            if (col < TVN)
                px[i] = *reinterpret_cast<const float4*>(&xb[(size_t)c * TVN + col]);
        }
    }

    for (int kc = 0; kc < 2; kc++) {
        if (kc > 0) __syncthreads();          // protect Xsm overwrite
#pragma unroll
        for (int i = 0; i < 3; i++) {
            int idx = tid + 384 * i;
            if (idx < 1024) {
                int c = idx >> 5, cc4 = (idx & 31) * 4;
                *reinterpret_cast<float4*>(&Xsm[c][cc4]) = px[i];
            }
        }
        __syncthreads();                      // Xsm (and Wt on kc=0) visible
        if (kc == 0) {                        // prefetch chunk 1 behind compute
#pragma unroll
            for (int i = 0; i < 3; i++) {
                int idx = tid + 384 * i;
                if (idx < 1024) {
                    int c = idx >> 5, cc4 = (idx & 31) * 4;
                    int col = col0 + cc4;
                    px[i] = make_float4(0.f, 0.f, 0.f, 0.f);
                    if (col < TVN)
                        px[i] = *reinterpret_cast<const float4*>(
                                    &xb[(size_t)(32 + c) * TVN + col]);
                }
            }
        }
#pragma unroll 8
        for (int kk = 0; kk < 32; kk++) {
            const float* wrow = &Wt[kc * 32 + kk][r0];
            u64 w01 = *reinterpret_cast<const u64*>(wrow + 0);
            u64 w23 = *reinterpret_cast<const u64*>(wrow + 2);
            u64 w45 = *reinterpret_cast<const u64*>(wrow + 4);
            u64 w67 = *reinterpret_cast<const u64*>(wrow + 6);
            float4 xq = *reinterpret_cast<const float4*>(&Xsm[kk][c4]);
            u64 xd[4];
            xd[0] = pk2(xq.x, xq.x); xd[1] = pk2(xq.y, xq.y);
            xd[2] = pk2(xq.z, xq.z); xd[3] = pk2(xq.w, xq.w);
#pragma unroll
            for (int q = 0; q < 4; q++) {
                fma2(acc[0][q], w01, xd[q]);
                fma2(acc[1][q], w23, xd[q]);
                fma2(acc[2][q], w45, xd[q]);
                fma2(acc[3][q], w67, xd[q]);
            }
        }
    }

    // epilogue: unpack pairs, add bias, store (bf16 for a/b, fp32 for z)
    const int col = col0 + c4;
    if (col < TVN) {
#pragma unroll
        for (int p = 0; p < 4; p++) {
            float2 f0 = upk(acc[p][0]);
            float2 f1 = upk(acc[p][1]);
            float2 f2 = upk(acc[p][2]);
            float2 f3 = upk(acc[p][3]);
#pragma unroll
            for (int h = 0; h < 2; h++) {
                int r = r0 + 2 * p + h;
                float vx = (h ? f0.y : f0.x);
                float vy = (h ? f1.y : f1.x);
                float vz = (h ? f2.y : f2.x);
                float vw = (h ? f3.y : f3.x);
                if (gz == 0) {
                    int which = (r >= 48);
                    int rr = which ? r - 48 : r;       // s*16 + ci
                    float bias = which ? bb[rr] : ba[rr];
                    int s = rr >> 4, ci = rr & 15;
                    __nv_bfloat16* dst = (which ? g_b : g_a) +
                        ((size_t)(s * NB + n) * CI + ci) * TVN;
                    __nv_bfloat162 lo = __floats2bfloat162_rn(vx + bias, vy + bias);
                    __nv_bfloat162 hi = __floats2bfloat162_rn(vz + bias, vw + bias);
                    uint2 st;
                    st.x = *reinterpret_cast<unsigned int*>(&lo);
                    st.y = *reinterpret_cast<unsigned int*>(&hi);
                    *reinterpret_cast<uint2*>(dst + col) = st;
                } else {
                    int zr = (gz - 1) * 96 + r;        // s*64 + o
                    int s = zr >> 6, o = zr & 63;
                    float* dst = g_z + ((size_t)(s * NB + n) * CO + o) * TVN;
                    float4 outv = make_float4(vx, vy, vz, vw);
                    *reinterpret_cast<float4*>(&dst[col]) = outv;
                }
            }
        }
    }
}

// ---------------------------------------------------------------------------
// Kernel 2a (k_attn_p1): split-K partial logits.
// ---------------------------------------------------------------------------
__global__ __launch_bounds__(256) void k_attn_p1()
{
    const int sn = blockIdx.x;          // s*64 + n
    const int sp = blockIdx.y;
    const __nv_bfloat16* Ab = g_a + (size_t)sn * (CI * TVN) + sp * 20000;
    const __nv_bfloat16* Bb = g_b + (size_t)sn * (CI * TVN) + sp * 20000;

    __shared__ float at[800];
    __shared__ float bt[800];

    const int tid = threadIdx.x;
    const int u   = tid / 5;
    const int v0  = (tid % 5) * 5;
    const bool act = (tid < 125);
    const bool ld  = (tid < 200);
    const int arrb = (tid >= 100);
    const int j    = arrb ? tid - 100 : tid;   // uint4 index 0..99

    float acc[5] = {0.f, 0.f, 0.f, 0.f, 0.f};

    uint4 p;
    if (ld)
        p = reinterpret_cast<const uint4*>(arrb ? Bb : Ab)[j];

    for (int kc = 0; kc < 25; kc++) {
        __syncthreads();
        if (ld) {
            float* dstf = (arrb ? bt : at) + j * 8;
            float2 f0 = __bfloat1622float2(*reinterpret_cast<__nv_bfloat162*>(&p.x));
            float2 f1 = __bfloat1622float2(*reinterpret_cast<__nv_bfloat162*>(&p.y));
            float2 f2 = __bfloat1622float2(*reinterpret_cast<__nv_bfloat162*>(&p.z));
            float2 f3 = __bfloat1622float2(*reinterpret_cast<__nv_bfloat162*>(&p.w));
            *reinterpret_cast<float2*>(dstf + 0) = f0;
            *reinterpret_cast<float2*>(dstf + 2) = f1;
            *reinterpret_cast<float2*>(dstf + 4) = f2;
            *reinterpret_cast<float2*>(dstf + 6) = f3;
        }
        __syncthreads();
        if (kc < 24 && ld)
            p = reinterpret_cast<const uint4*>((arrb ? Bb : Ab) + (kc + 1) * 800)[j];
        if (act) {
#pragma unroll 8
            for (int kk = 0; kk < 32; kk++) {
                float av = at[kk * 25 + u];
#pragma unroll
                for (int jj = 0; jj < 5; jj++)
                    acc[jj] = fmaf(av, bt[kk * 25 + v0 + jj], acc[jj]);
            }
        }
    }

    if (act) {
        float* dst = g_part + ((size_t)sn * SPLITS + sp) * 625 + u * 25 + v0;
#pragma unroll
        for (int jj = 0; jj < 5; jj++) dst[jj] = acc[jj];
    }
}

// ---------------------------------------------------------------------------
// Kernel 2b (k_attn_p2): reduce partials, softmax over u, + (Ast+Gat), store.
// ---------------------------------------------------------------------------
__global__ __launch_bounds__(128) void k_attn_p2(
    const float* __restrict__ Ast, const float* __restrict__ Gat)
{
    const int sn = blockIdx.x;
    const int s  = sn >> 6;
    __shared__ float Gsm[625];
    const int tid = threadIdx.x;

    if (tid < 125) {
        int u = tid / 5, v0 = (tid % 5) * 5;
#pragma unroll
        for (int jj = 0; jj < 5; jj++) {
            float sum = 0.f;
#pragma unroll
            for (int sp = 0; sp < SPLITS; sp++)
                sum += g_part[((size_t)sn * SPLITS + sp) * 625 + u * 25 + v0 + jj];
            Gsm[u * 25 + v0 + jj] = sum * (1.0f / 4800.0f);
        }
    }
    __syncthreads();

    if (tid < 25) {
        const int v = tid;
        float m = -INFINITY;
        for (int uu = 0; uu < 25; uu++) m = fmaxf(m, Gsm[uu * 25 + v]);
        float ssum = 0.f;
        for (int uu = 0; uu < 25; uu++) {
            float e = expf(Gsm[uu * 25 + v] - m);
            Gsm[uu * 25 + v] = e;
            ssum += e;
        }
        float sinv = 1.0f / ssum;
        float* dst = g_attn + (size_t)sn * 625;
        const float* a1 = Ast + s * 625;
        const float* a2 = Gat + s * 625;
        for (int uu = 0; uu < 25; uu++) {
            int i = uu * 25 + v;
            dst[i] = Gsm[i] * sinv + a1[i] + a2[i];
        }
    }
}

// ---------------------------------------------------------------------------
// Kernel 3 (k_out2): out[o,t,v] = relu( BN( sum_{s,u} z[s,o,t,u]*attn[s,u,v]
//                                         + sum_s bg[s,o] ) + x )
// Per-s staged zsm (26 KB) -> 4 blocks/SM. Attn pre-packed as lane-dup u64.
// ---------------------------------------------------------------------------
#define ZS 260    // zsm row stride (floats)
#define ATN_OFF 1876   // u64 slots reserved for packed attn (16B-aligned end)

__global__ __launch_bounds__(320) void k_out2(
    const float* __restrict__ x,
    const float* __restrict__ bg,
    const float* __restrict__ gamma, const float* __restrict__ beta,
    const float* __restrict__ rmean, const float* __restrict__ rvar,
    float* __restrict__ out)
{
    extern __shared__ u64 smu[];
    u64*   atn2 = smu;                          // 75*25 packed attn (u64), pad to 1876
    float* zsm  = (float*)(smu + ATN_OFF);      // 25*260 floats (one s at a time)
    float* sc   = zsm + 25 * ZS;                // 64
    float* sh   = sc + 64;                      // 64
    float* osm  = zsm;                          // 64*100 reuse after mainloop

    const int n   = blockIdx.y;
    const int t0  = blockIdx.x * 4;
    const int tid = threadIdx.x;

    // attn -> packed smem table: atn2[(s*25+u)*25 + v] = (val, val)
    for (int idx = tid; idx < 1875; idx += 320) {
        int s = idx / 625, rem = idx - s * 625;    // rem = u*25+v
        float val = g_attn[(size_t)(s * NB + n) * 625 + rem];
        atn2[s * 625 + rem] = pk2(val, val);
    }
    if (tid < 64) {
        float inv = rsqrtf(rvar[tid] + 1e-5f);
        float s0 = gamma[tid] * inv;
        float bsum = bg[tid] + bg[64 + tid] + bg[128 + tid];
        sc[tid] = s0;
        sh[tid] = beta[tid] + (bsum - rmean[tid]) * s0;
    }

    const int rg = tid / 5, cg = tid - rg * 5;
    const int r0 = rg * 4, v0 = cg * 5;
    const int t  = r0 >> 6, o0 = r0 & 63;

    u64 a2[2][5];
#pragma unroll
    for (int i = 0; i < 2; i++)
#pragma unroll
        for (int j = 0; j < 5; j++) a2[i][j] = 0ull;

    for (int s = 0; s < NS; s++) {
        if (s) __syncthreads();                 // previous compute done
        // stage z(s): zsm[u][tt*64+o]  via float4 loads of g_z rows
        const float* zb = g_z + ((size_t)(s * NB + n) * CO) * TVN + (size_t)t0 * 25;
        for (int fidx = tid; fidx < 1600; fidx += 320) {
            int o = fidx / 25, f = fidx - o * 25;
            float4 v = *reinterpret_cast<const float4*>(&zb[(size_t)o * TVN + f * 4]);
            const float* vp = reinterpret_cast<const float*>(&v);
#pragma unroll
            for (int j = 0; j < 4; j++) {
                int pos = f * 4 + j;                  // pos = tt*25+u, < 100
                int tt = pos / 25, u = pos - tt * 25;
                zsm[u * ZS + tt * 64 + o] = vp[j];
            }
        }
        __syncthreads();                        // zsm (+atn2/sc on s=0) visible
        const u64* ab = atn2 + s * 625 + v0;
#pragma unroll 5
        for (int u = 0; u < 25; u++) {
            const float* zr = &zsm[u * ZS + r0];
            u64 z01 = *reinterpret_cast<const u64*>(zr + 0);
            u64 z23 = *reinterpret_cast<const u64*>(zr + 2);
            const u64* ar = ab + u * 25;
#pragma unroll
            for (int j = 0; j < 5; j++) {
                u64 ad = ar[j];
                fma2(a2[0][j], z01, ad);
                fma2(a2[1][j], z23, ad);
            }
        }
    }
    __syncthreads();                            // all zsm reads done

    // stage result tile into smem: osm[o][t*25+v]
#pragma unroll
    for (int i = 0; i < 4; i++) {
        int o = o0 + i;
#pragma unroll
        for (int j = 0; j < 5; j++) {
            float2 f = upk(a2[i >> 1][j]);
            osm[o * 100 + t * 25 + v0 + j] = (i & 1) ? f.y : f.x;
        }
    }
    __syncthreads();

    // coalesced epilogue: per o, the 100 cols are contiguous in gmem
    const float* xb = x + (size_t)n * CIN * TVN + (size_t)t0 * 25;
    float* ob = out + (size_t)n * CIN * TVN + (size_t)t0 * 25;
    for (int fidx = tid; fidx < 1600; fidx += 320) {
        int o = fidx / 25, f = fidx - o * 25;
        float4 r = *reinterpret_cast<const float4*>(&osm[o * 100 + f * 4]);
        float4 xv = *reinterpret_cast<const float4*>(&xb[(size_t)o * TVN + f * 4]);
        float s0 = sc[o], h0 = sh[o];
        float4 ov;
        ov.x = fmaxf(r.x * s0 + h0 + xv.x, 0.f);
        ov.y = fmaxf(r.y * s0 + h0 + xv.y, 0.f);
        ov.z = fmaxf(r.z * s0 + h0 + xv.z, 0.f);
        ov.w = fmaxf(r.w * s0 + h0 + xv.w, 0.f);
        *reinterpret_cast<float4*>(&ob[(size_t)o * TVN + f * 4]) = ov;
    }
}

// ---------------------------------------------------------------------------
extern "C" void kernel_launch(void* const* d_in, const int* in_sizes, int n_in,
                              void* d_out, int out_size)
{
    const float* x     = (const float*)d_in[0];
    const float* Ast   = (const float*)d_in[1];
    const float* Gat   = (const float*)d_in[2];
    const float* Wg    = (const float*)d_in[3];
    const float* bg    = (const float*)d_in[4];
    const float* Wa    = (const float*)d_in[5];
    const float* ba    = (const float*)d_in[6];
    const float* Wb    = (const float*)d_in[7];
    const float* bb    = (const float*)d_in[8];
    const float* gamma = (const float*)d_in[9];
    const float* beta  = (const float*)d_in[10];
    const float* rmean = (const float*)d_in[11];
    const float* rvar  = (const float*)d_in[12];
    float* out = (float*)d_out;

    (void)in_sizes; (void)n_in; (void)out_size;

    const int smem_k3 = ATN_OFF * 8 + (25 * ZS + 128) * (int)sizeof(float);
    cudaFuncSetAttribute(k_out2, cudaFuncAttributeMaxDynamicSharedMemorySize, smem_k3);

    k_mm<<<dim3(59, 64, 3), 384>>>(x, Wa, ba, Wb, bb, Wg);
    k_attn_p1<<<dim3(192, SPLITS), 256>>>();
    k_attn_p2<<<192, 128>>>(Ast, Gat);
    k_out2<<<dim3(75, 64), 320, smem_k3>>>(x, bg, gamma, beta, rmean, rvar, out);
}